// round 9
// baseline (speedup 1.0000x reference)
#include <cuda_runtime.h>
#include <math.h>

#define C_DIM   256
#define MED_DIM 128
#define HW_DIM  6400
#define B_DIM   16
#define K_OUT   128
#define P_PIX   32
#define NTHREADS 256

// smem layout in floats
#define OFF_XS   0          // [256][32] x tile                 (8192 f)
#define OFF_XL   8192       // [256][32] x_ tile / w1 staging   (8192 f)
#define OFF_H    16384      // [128][32] h tile                 (4096 f)
#define OFF_TAIL 20480      // w2 staging (4096 f)
#define OFF_KEYS 16384      // keys alias h+tail (8192 f), used after GEMMs
#define OFF_SIDX 24576      // sidx: 2048 floats = 8192 bytes
#define SMEM_FLOATS 26624
#define SMEM_BYTES (SMEM_FLOATS * 4)

// Pre-transposed weights (transpose only: NO arithmetic, keeps bits identical)
__device__ float d_w1t[C_DIM * MED_DIM];   // w1t[c][m]  = w1[m][c]
__device__ float d_w2t[MED_DIM * C_DIM];   // w2t[m][c'] = w2[c'][m]
__device__ float d_b1[MED_DIM];
__device__ float d_b2[C_DIM];

__global__ void prep_kernel(const float* __restrict__ w1, const float* __restrict__ b1,
                            const float* __restrict__ w2, const float* __restrict__ b2) {
    int bidx = blockIdx.x;      // 0..255
    int t = threadIdx.x;        // 0..255
    if (t < MED_DIM)  d_w1t[bidx * MED_DIM + t] = w1[t * C_DIM + bidx];
    if (bidx < MED_DIM) d_w2t[bidx * C_DIM + t] = w2[t * MED_DIM + bidx];
    if (bidx == 0 && t < MED_DIM) d_b1[t] = b1[t];
    if (bidx == 1) d_b2[t] = b2[t];
}

// ---- Bit-exact replica of XLA:CPU vectorized exp (Cephes / sse_mathfun lineage) ----
// fx = floor(fma(x, log2e, 0.5)); two-step Cody-Waite reduction via FMA;
// 6-coef Horner (FMA); y = fma(P, r^2, r) + 1; scale by 2^fx via exponent bits.
__device__ __forceinline__ float ref_expf(float v) {
    v = fminf(v, 88.3762626647950f);
    v = fmaxf(v, -88.3762626647949f);
    float fx = floorf(__fmaf_rn(v, 1.44269504088896341f, 0.5f));
    float x  = __fmaf_rn(fx, -0.693359375f, v);
    x = __fmaf_rn(fx, 2.12194440e-4f, x);
    float x2 = __fmul_rn(x, x);
    float y = 1.9875691500E-4f;
    y = __fmaf_rn(y, x, 1.3981999507E-3f);
    y = __fmaf_rn(y, x, 8.3334519073E-3f);
    y = __fmaf_rn(y, x, 4.1665795894E-2f);
    y = __fmaf_rn(y, x, 1.6666665459E-1f);
    y = __fmaf_rn(y, x, 5.0000001201E-1f);
    y = __fmaf_rn(y, x2, x);
    y = __fadd_rn(y, 1.0f);
    int n = (int)fx;
    float s = __int_as_float((n + 127) << 23);   // 2^n (|n| small here: x_ in ~[-4,4])
    return __fmul_rn(y, s);
}

// logistic(x) = 1 / (1 + exp(-x)), IEEE rn add/div, exact negation
__device__ __forceinline__ float sigmoid_xla(float x) {
    float e = ref_expf(-x);
    return __fdiv_rn(1.0f, __fadd_rn(1.0f, e));
}

extern __shared__ float smem[];

__global__ void __launch_bounds__(NTHREADS, 2)
csc_main_kernel(const float* __restrict__ x, float* __restrict__ out) {
    float* xs = smem + OFF_XS;
    float* xl = smem + OFF_XL;
    float* hb = smem + OFF_H;
    float* w1s = smem + OFF_XL;                     // alias: w1 staging during stage A
    float* w2s = smem + OFF_TAIL;                   // w2 staging during stage B
    unsigned int* keys = (unsigned int*)(smem + OFF_KEYS);
    unsigned char* sidx = (unsigned char*)(smem + OFF_SIDX);

    const int t   = threadIdx.x;
    const int bid = blockIdx.x;
    const int bb  = bid / 200;
    const int hw0 = (bid % 200) * P_PIX;

    const int tx = t & 7;       // pixel group: p = tx*4..+3
    const int ty = t >> 3;      // 0..31

    // ---- load x tile [256][32], coalesced float4 ----
    const float* xg = x + ((size_t)bb * C_DIM) * HW_DIM + hw0;
    for (int i = t; i < C_DIM * 8; i += NTHREADS) {
        int c = i >> 3, seg = i & 7;
        ((float4*)xs)[c * 8 + seg] = *(const float4*)(xg + (size_t)c * HW_DIM + seg * 4);
    }

    // ================= Stage A: h[m][p] = sum_c w1[m][c]*x[c][p]  (c ascending, FMA) =====
    // thread owns m = ty*4..+3, p = tx*4..+3
    float a[4][4];
#pragma unroll
    for (int i = 0; i < 4; ++i)
#pragma unroll
        for (int j = 0; j < 4; ++j) a[i][j] = 0.f;

    for (int c0 = 0; c0 < C_DIM; c0 += 64) {
        __syncthreads();
        // stage w1t[c0..c0+63][0..127] -> w1s (8192 floats), coalesced
        for (int i = t; i < 2048; i += NTHREADS)
            ((float4*)w1s)[i] = ((const float4*)d_w1t)[c0 * 32 + i];
        __syncthreads();
#pragma unroll 4
        for (int cc = 0; cc < 64; ++cc) {
            float4 wv = ((const float4*)w1s)[cc * 32 + ty];   // w1t[c0+cc][ty*4..+3]
            float4 xv = ((const float4*)xs)[(c0 + cc) * 8 + tx];
            float wr[4] = {wv.x, wv.y, wv.z, wv.w};
            float xr[4] = {xv.x, xv.y, xv.z, xv.w};
#pragma unroll
            for (int i = 0; i < 4; ++i)
#pragma unroll
                for (int j = 0; j < 4; ++j)
                    a[i][j] = __fmaf_rn(wr[i], xr[j], a[i][j]);
        }
    }
    __syncthreads();
    // h = acc + b1  (single rounded add, like reference bias broadcast)
#pragma unroll
    for (int i = 0; i < 4; ++i) {
        int m = ty * 4 + i;
        float bs = d_b1[m];
#pragma unroll
        for (int j = 0; j < 4; ++j)
            hb[m * P_PIX + tx * 4 + j] = __fadd_rn(a[i][j], bs);
    }

    // ================= Stage B: x_[c'][p] = sum_m w2[c'][m]*h[m][p]  (m ascending, FMA) ===
    // thread owns c' = ty*8..+7, p = tx*4..+3
    float b[8][4];
#pragma unroll
    for (int i = 0; i < 8; ++i)
#pragma unroll
        for (int j = 0; j < 4; ++j) b[i][j] = 0.f;

    for (int m0 = 0; m0 < MED_DIM; m0 += 16) {
        __syncthreads();
        // stage w2t[m0..m0+15][0..255] -> w2s (4096 floats), coalesced
        for (int i = t; i < 1024; i += NTHREADS)
            ((float4*)w2s)[i] = ((const float4*)d_w2t)[m0 * 64 + i];
        __syncthreads();
#pragma unroll 4
        for (int mm = 0; mm < 16; ++mm) {
            float4 hv = ((const float4*)hb)[(m0 + mm) * 8 + tx];
            float4 w0 = ((const float4*)w2s)[mm * 64 + ty * 2];
            float4 w1v = ((const float4*)w2s)[mm * 64 + ty * 2 + 1];
            float wr[8] = {w0.x, w0.y, w0.z, w0.w, w1v.x, w1v.y, w1v.z, w1v.w};
            float hr[4] = {hv.x, hv.y, hv.z, hv.w};
#pragma unroll
            for (int i = 0; i < 8; ++i)
#pragma unroll
                for (int j = 0; j < 4; ++j)
                    b[i][j] = __fmaf_rn(wr[i], hr[j], b[i][j]);
        }
    }

    // ---- epilogue: bias, write x_ tile ----
    float v[8][4];
#pragma unroll
    for (int i = 0; i < 8; ++i) {
        int cp = ty * 8 + i;
        float bs = d_b2[cp];
#pragma unroll
        for (int j = 0; j < 4; ++j) {
            v[i][j] = __fadd_rn(b[i][j], bs);
            xl[cp * P_PIX + tx * 4 + j] = v[i][j];
        }
    }
    __syncthreads();   // all h/w2s readers done -> safe to write keys (alias)

    // keys = bits(sigmoid(x_)) (positive floats -> monotone as uint)
#pragma unroll
    for (int i = 0; i < 8; ++i) {
        int cp = ty * 8 + i;
#pragma unroll
        for (int j = 0; j < 4; ++j)
            keys[cp * P_PIX + tx * 4 + j] = __float_as_uint(sigmoid_xla(v[i][j]));
    }
    for (int i = t; i < C_DIM * P_PIX; i += NTHREADS)
        sidx[i] = (unsigned char)(i >> 5);
    __syncthreads();

    // ---- bitonic sort per pixel: descending by (key, then ascending channel) ----
    for (int k = 2; k <= 256; k <<= 1) {
        for (int j = k >> 1; j > 0; j >>= 1) {
#pragma unroll 1
            for (int it = 0; it < 16; ++it) {
                int task = t + NTHREADS * it;       // 0..4095
                int p = task & 31;
                int l = task >> 5;                  // 0..127
                int i = ((l & ~(j - 1)) << 1) | (l & (j - 1));
                int pr = i | j;
                unsigned int ka = keys[i * P_PIX + p];
                unsigned int kb = keys[pr * P_PIX + p];
                unsigned char ia = sidx[i * P_PIX + p];
                unsigned char ib = sidx[pr * P_PIX + p];
                bool aFirst = (ka > kb) || (ka == kb && ia < ib);
                bool wantAFirst = ((i & k) == 0);
                if (aFirst != wantAFirst) {
                    keys[i * P_PIX + p] = kb; keys[pr * P_PIX + p] = ka;
                    sidx[i * P_PIX + p] = ib; sidx[pr * P_PIX + p] = ia;
                }
            }
            __syncthreads();
        }
    }

    // ---- gather + write: out[b, r, hw] = x[c_r]*x_[c_r] ----
    for (int it = 0; it < 16; ++it) {
        int task = t + NTHREADS * it;   // 128 ranks x 32 pixels
        int p = task & 31, r = task >> 5;
        int c = sidx[r * P_PIX + p];
        float vo = __fmul_rn(xs[c * P_PIX + p], xl[c * P_PIX + p]);
        out[((size_t)(bb * K_OUT + r)) * HW_DIM + hw0 + p] = vo;
    }
}

extern "C" void kernel_launch(void* const* d_in, const int* in_sizes, int n_in,
                              void* d_out, int out_size) {
    const float* x  = (const float*)d_in[0];
    const float* w1 = (const float*)d_in[1];
    const float* b1 = (const float*)d_in[2];
    const float* w2 = (const float*)d_in[3];
    const float* b2 = (const float*)d_in[4];
    float* out = (float*)d_out;

    cudaFuncSetAttribute(csc_main_kernel,
                         cudaFuncAttributeMaxDynamicSharedMemorySize, SMEM_BYTES);
    prep_kernel<<<C_DIM, NTHREADS>>>(w1, b1, w2, b2);
    csc_main_kernel<<<(B_DIM * HW_DIM) / P_PIX, NTHREADS, SMEM_BYTES>>>(x, out);
}

// round 10
// speedup vs baseline: 1.2288x; 1.2288x over previous
#include <cuda_runtime.h>
#include <math.h>

#define C_DIM   256
#define MED_DIM 128
#define HW_DIM  6400
#define B_DIM   16
#define K_OUT   128
#define P_PIX   32
#define NTHREADS 256
#define XSS     36          // xs row stride in floats (padded: 9c+p/4 banks ~uniform)

// smem layout in floats
#define OFF_XS   0                          // xs [256][36]          9216 f
#define OFF_XLT  9216                       // w1s staging (8192) -> xl_t [32][256]
#define OFF_W    17408                      // w2s (4096) | hb at +4096 (4096) | later prod (4224)
#define OFF_SIDX 25600                      // sidx2: 8192 bytes = 2048 f
#define SMEM_FLOATS 27648
#define SMEM_BYTES (SMEM_FLOATS * 4)        // 108 KB -> 2 CTAs/SM

// Pre-transposed weights (transpose only: NO arithmetic, keeps bits identical)
__device__ float d_w1t[C_DIM * MED_DIM];   // w1t[c][m]  = w1[m][c]
__device__ float d_w2t[MED_DIM * C_DIM];   // w2t[m][c'] = w2[c'][m]
__device__ float d_b1[MED_DIM];
__device__ float d_b2[C_DIM];

__global__ void prep_kernel(const float* __restrict__ w1, const float* __restrict__ b1,
                            const float* __restrict__ w2, const float* __restrict__ b2) {
    int bidx = blockIdx.x;      // 0..255
    int t = threadIdx.x;        // 0..255
    if (t < MED_DIM)  d_w1t[bidx * MED_DIM + t] = w1[t * C_DIM + bidx];
    if (bidx < MED_DIM) d_w2t[bidx * C_DIM + t] = w2[t * MED_DIM + bidx];
    if (bidx == 0 && t < MED_DIM) d_b1[t] = b1[t];
    if (bidx == 1) d_b2[t] = b2[t];
}

// ---- Bit-exact replica of XLA:CPU vectorized exp (Cephes / sse_mathfun lineage) ----
__device__ __forceinline__ float ref_expf(float v) {
    v = fminf(v, 88.3762626647950f);
    v = fmaxf(v, -88.3762626647949f);
    float fx = floorf(__fmaf_rn(v, 1.44269504088896341f, 0.5f));
    float x  = __fmaf_rn(fx, -0.693359375f, v);
    x = __fmaf_rn(fx, 2.12194440e-4f, x);
    float x2 = __fmul_rn(x, x);
    float y = 1.9875691500E-4f;
    y = __fmaf_rn(y, x, 1.3981999507E-3f);
    y = __fmaf_rn(y, x, 8.3334519073E-3f);
    y = __fmaf_rn(y, x, 4.1665795894E-2f);
    y = __fmaf_rn(y, x, 1.6666665459E-1f);
    y = __fmaf_rn(y, x, 5.0000001201E-1f);
    y = __fmaf_rn(y, x2, x);
    y = __fadd_rn(y, 1.0f);
    int n = (int)fx;
    float s = __int_as_float((n + 127) << 23);
    return __fmul_rn(y, s);
}

__device__ __forceinline__ float sigmoid_xla(float x) {
    float e = ref_expf(-x);
    return __fdiv_rn(1.0f, __fadd_rn(1.0f, e));
}

// one local bitonic level (distance J < 8, register-resident), runtime k
template<int J>
__device__ __forceinline__ void local_level(unsigned long long P[8], int k, int lane) {
#pragma unroll
    for (int r = 0; r < 8; ++r) {
        if ((r & J) == 0) {
            int r2 = r | J;
            bool up = ((((lane << 3) | r) & k) == 0);   // keep max at lower e
            unsigned long long a = P[r], b = P[r2];
            bool g = a > b;
            unsigned long long mx = g ? a : b;
            unsigned long long mn = g ? b : a;
            P[r]  = up ? mx : mn;
            P[r2] = up ? mn : mx;
        }
    }
}

extern __shared__ float smem[];

__global__ void __launch_bounds__(NTHREADS, 2)
csc_main_kernel(const float* __restrict__ x, float* __restrict__ out) {
    float* xs   = smem + OFF_XS;                 // [256][XSS]
    float* xl_t = smem + OFF_XLT;                // [32][256], after epilogue
    float* w1s  = smem + OFF_XLT;                // alias: stage A staging
    float* w2s  = smem + OFF_W;                  // stage B staging
    float* hb   = smem + OFF_W + 4096;           // [128][32] h tile
    float* prod = smem + OFF_W;                  // alias: [128][33] products (post-sort)
    unsigned char* sidx2 = (unsigned char*)(smem + OFF_SIDX);   // [32][256]

    const int t   = threadIdx.x;
    const int bid = blockIdx.x;
    const int bb  = bid / 200;
    const int hw0 = (bid % 200) * P_PIX;

    const int tx = t & 7;       // pixel group: p = tx*4..+3
    const int ty = t >> 3;      // 0..31
    const int lane = t & 31;
    const int warp = t >> 5;

    // ---- load x tile [256][XSS], coalesced float4 ----
    const float* xg = x + ((size_t)bb * C_DIM) * HW_DIM + hw0;
    for (int i = t; i < C_DIM * 8; i += NTHREADS) {
        int c = i >> 3, seg = i & 7;
        ((float4*)xs)[c * 9 + seg] = *(const float4*)(xg + (size_t)c * HW_DIM + seg * 4);
    }

    // ========== Stage A: h[m][p] = sum_c w1[m][c]*x[c][p]  (c ascending, FMA) ==========
    float a[4][4];
#pragma unroll
    for (int i = 0; i < 4; ++i)
#pragma unroll
        for (int j = 0; j < 4; ++j) a[i][j] = 0.f;

    for (int c0 = 0; c0 < C_DIM; c0 += 64) {
        __syncthreads();
        for (int i = t; i < 2048; i += NTHREADS)
            ((float4*)w1s)[i] = ((const float4*)d_w1t)[c0 * 32 + i];
        __syncthreads();
#pragma unroll 4
        for (int cc = 0; cc < 64; ++cc) {
            float4 wv = ((const float4*)w1s)[cc * 32 + ty];
            float4 xv = ((const float4*)xs)[(c0 + cc) * 9 + tx];
            float wr[4] = {wv.x, wv.y, wv.z, wv.w};
            float xr[4] = {xv.x, xv.y, xv.z, xv.w};
#pragma unroll
            for (int i = 0; i < 4; ++i)
#pragma unroll
                for (int j = 0; j < 4; ++j)
                    a[i][j] = __fmaf_rn(wr[i], xr[j], a[i][j]);
        }
    }
    // hb lives in its own region (no alias with w1s/xs) -> safe to write now
#pragma unroll
    for (int i = 0; i < 4; ++i) {
        int m = ty * 4 + i;
        float bs = d_b1[m];
#pragma unroll
        for (int j = 0; j < 4; ++j)
            hb[m * P_PIX + tx * 4 + j] = __fadd_rn(a[i][j], bs);
    }

    // ========== Stage B: x_[c'][p] = sum_m w2[c'][m]*h[m][p]  (m ascending, FMA) ==========
    float b[8][4];
#pragma unroll
    for (int i = 0; i < 8; ++i)
#pragma unroll
        for (int j = 0; j < 4; ++j) b[i][j] = 0.f;

    for (int m0 = 0; m0 < MED_DIM; m0 += 16) {
        __syncthreads();
        for (int i = t; i < 1024; i += NTHREADS)
            ((float4*)w2s)[i] = ((const float4*)d_w2t)[m0 * 64 + i];
        __syncthreads();
#pragma unroll 4
        for (int mm = 0; mm < 16; ++mm) {
            float4 hv = ((const float4*)hb)[(m0 + mm) * 8 + tx];
            float4 w0 = ((const float4*)w2s)[mm * 64 + ty * 2];
            float4 w1v = ((const float4*)w2s)[mm * 64 + ty * 2 + 1];
            float wr[8] = {w0.x, w0.y, w0.z, w0.w, w1v.x, w1v.y, w1v.z, w1v.w};
            float hr[4] = {hv.x, hv.y, hv.z, hv.w};
#pragma unroll
            for (int i = 0; i < 8; ++i)
#pragma unroll
                for (int j = 0; j < 4; ++j)
                    b[i][j] = __fmaf_rn(wr[i], hr[j], b[i][j]);
        }
    }

    // ---- epilogue: bias, write x_ transposed [p][c] (w1s region long dead) ----
#pragma unroll
    for (int i = 0; i < 8; ++i) {
        int cp = ty * 8 + i;
        float bs = d_b2[cp];
#pragma unroll
        for (int j = 0; j < 4; ++j) {
            float v = __fadd_rn(b[i][j], bs);
            xl_t[(tx * 4 + j) * 256 + cp] = v;
        }
    }
    __syncthreads();

    // ========== register-resident bitonic sort: one warp per pixel (4 px/warp) ==========
    // element e = lane*8 + r ; P = (sigmoid_bits << 8) | (255 ^ c) ; descending => key desc, c asc
    for (int q = 0; q < 4; ++q) {
        int p = warp * 4 + q;
        const float* row = xl_t + p * 256 + lane * 8;
        float4 v0 = *(const float4*)row;
        float4 v1 = *(const float4*)(row + 4);
        float vv[8] = {v0.x, v0.y, v0.z, v0.w, v1.x, v1.y, v1.z, v1.w};
        unsigned long long P[8];
#pragma unroll
        for (int r = 0; r < 8; ++r) {
            unsigned int kb = __float_as_uint(sigmoid_xla(vv[r]));
            P[r] = ((unsigned long long)kb << 8) |
                   (unsigned long long)(0xFF ^ (lane * 8 + r));
        }

#pragma unroll 1
        for (int k = 2; k <= 256; k <<= 1) {
#pragma unroll 1
            for (int j = k >> 1; j >= 8; j >>= 1) {
                int m = j >> 3;
                bool km = ((lane & (k >> 3)) == 0) == ((lane & m) == 0);
#pragma unroll
                for (int r = 0; r < 8; ++r) {
                    unsigned long long qv = __shfl_xor_sync(0xFFFFFFFFu, P[r], m);
                    bool g = P[r] > qv;
                    P[r] = (g == km) ? P[r] : qv;
                }
            }
            if (k >= 8) {
                local_level<4>(P, k, lane);
                local_level<2>(P, k, lane);
                local_level<1>(P, k, lane);
            } else if (k == 4) {
                local_level<2>(P, k, lane);
                local_level<1>(P, k, lane);
            } else {
                local_level<1>(P, k, lane);
            }
        }

        // element e now holds rank e; emit channel bytes, ranks lane*8..lane*8+7
        unsigned long long wbits = 0;
#pragma unroll
        for (int r = 0; r < 8; ++r)
            wbits |= (unsigned long long)(0xFFu ^ (unsigned)(P[r] & 0xFFu)) << (8 * r);
        *(unsigned long long*)(sidx2 + p * 256 + lane * 8) = wbits;
    }
    __syncthreads();

    // ---- gather (rank-major lanes): prod[r][p] = x[c]*x_[c] ; stride-33 staging ----
    for (int it = 0; it < 16; ++it) {
        int task = t + NTHREADS * it;      // 32 px * 128 ranks
        int r = task & 127;
        int p = task >> 7;
        int c = sidx2[p * 256 + r];
        prod[r * 33 + p] = __fmul_rn(xs[c * XSS + p], xl_t[p * 256 + c]);
    }
    __syncthreads();

    // ---- write (pixel-major lanes): fully coalesced ----
    for (int it = 0; it < 16; ++it) {
        int task = t + NTHREADS * it;
        int p = task & 31;
        int rr = task >> 5;
        out[((size_t)(bb * K_OUT + rr)) * HW_DIM + hw0 + p] = prod[rr * 33 + p];
    }
}

extern "C" void kernel_launch(void* const* d_in, const int* in_sizes, int n_in,
                              void* d_out, int out_size) {
    const float* x  = (const float*)d_in[0];
    const float* w1 = (const float*)d_in[1];
    const float* b1 = (const float*)d_in[2];
    const float* w2 = (const float*)d_in[3];
    const float* b2 = (const float*)d_in[4];
    float* out = (float*)d_out;

    cudaFuncSetAttribute(csc_main_kernel,
                         cudaFuncAttributeMaxDynamicSharedMemorySize, SMEM_BYTES);
    prep_kernel<<<C_DIM, NTHREADS>>>(w1, b1, w2, b2);
    csc_main_kernel<<<(B_DIM * HW_DIM) / P_PIX, NTHREADS, SMEM_BYTES>>>(x, out);
}

// round 11
// speedup vs baseline: 1.4922x; 1.2144x over previous
#include <cuda_runtime.h>
#include <math.h>
#include <stdint.h>

#define C_DIM   256
#define MED_DIM 128
#define HW_DIM  6400
#define B_DIM   16
#define K_OUT   128
#define P_PIX   32
#define NTHREADS 256
#define XSS     36          // xs row stride in floats (9 float4)

// smem layout in floats
#define OFF_XS   0                          // xs [256][36]          9216 f
#define OFF_XLT  9216                       // w1s staging (8192) -> xl_t [32][256]
#define OFF_W    17408                      // w2s (4096) | hb at +4096 (4096) | later prod (4224)
#define OFF_SIDX 25600                      // sidx2: 8192 bytes = 2048 f
#define SMEM_FLOATS 27648
#define SMEM_BYTES (SMEM_FLOATS * 4)        // 108 KB -> 2 CTAs/SM

// Pre-transposed weights (transpose only: NO arithmetic, keeps bits identical)
__device__ float d_w1t[C_DIM * MED_DIM];   // w1t[c][m]  = w1[m][c]
__device__ float d_w2t[MED_DIM * C_DIM];   // w2t[m][c'] = w2[c'][m]
__device__ float d_b1[MED_DIM];
__device__ float d_b2[C_DIM];

__global__ void prep_kernel(const float* __restrict__ w1, const float* __restrict__ b1,
                            const float* __restrict__ w2, const float* __restrict__ b2) {
    int bidx = blockIdx.x;      // 0..255
    int t = threadIdx.x;        // 0..255
    if (t < MED_DIM)  d_w1t[bidx * MED_DIM + t] = w1[t * C_DIM + bidx];
    if (bidx < MED_DIM) d_w2t[bidx * C_DIM + t] = w2[t * MED_DIM + bidx];
    if (bidx == 0 && t < MED_DIM) d_b1[t] = b1[t];
    if (bidx == 1) d_b2[t] = b2[t];
}

// ---- Bit-exact replica of XLA:CPU vectorized exp (Cephes / sse_mathfun lineage) ----
__device__ __forceinline__ float ref_expf(float v) {
    v = fminf(v, 88.3762626647950f);
    v = fmaxf(v, -88.3762626647949f);
    float fx = floorf(__fmaf_rn(v, 1.44269504088896341f, 0.5f));
    float x  = __fmaf_rn(fx, -0.693359375f, v);
    x = __fmaf_rn(fx, 2.12194440e-4f, x);
    float x2 = __fmul_rn(x, x);
    float y = 1.9875691500E-4f;
    y = __fmaf_rn(y, x, 1.3981999507E-3f);
    y = __fmaf_rn(y, x, 8.3334519073E-3f);
    y = __fmaf_rn(y, x, 4.1665795894E-2f);
    y = __fmaf_rn(y, x, 1.6666665459E-1f);
    y = __fmaf_rn(y, x, 5.0000001201E-1f);
    y = __fmaf_rn(y, x2, x);
    y = __fadd_rn(y, 1.0f);
    int n = (int)fx;
    float s = __int_as_float((n + 127) << 23);
    return __fmul_rn(y, s);
}

__device__ __forceinline__ float sigmoid_xla(float x) {
    float e = ref_expf(-x);
    return __fdiv_rn(1.0f, __fadd_rn(1.0f, e));
}

// ---- cp.async helpers ----
__device__ __forceinline__ void cp16(uint32_t dst, const void* src) {
    asm volatile("cp.async.ca.shared.global [%0], [%1], 16;" :: "r"(dst), "l"(src));
}
__device__ __forceinline__ void cp_wait_all() {
    asm volatile("cp.async.commit_group;\n\tcp.async.wait_group 0;" ::: "memory");
}

// compare-exchange: after call, a holds the element that should come FIRST
// in this block's direction. up=true means larger-first at 'a'.
__device__ __forceinline__ void ce(unsigned long long& a, unsigned long long& b, bool up) {
    unsigned long long x = a, y = b;
    bool g = (x > y) == up;
    a = g ? x : y;
    b = g ? y : x;
}

extern __shared__ float smem[];

__global__ void __launch_bounds__(NTHREADS, 2)
csc_main_kernel(const float* __restrict__ x, float* __restrict__ out) {
    float* xs   = smem + OFF_XS;                 // [256][XSS]
    float* xl_t = smem + OFF_XLT;                // [32][256], after epilogue
    float* w2s  = smem + OFF_W;                  // stage B staging
    float* hb   = smem + OFF_W + 4096;           // [128][32] h tile
    float* prod = smem + OFF_W;                  // alias: [128][33] products (post-sort)
    unsigned char* sidx2 = (unsigned char*)(smem + OFF_SIDX);   // [32][256]

    const uint32_t smem_u = (uint32_t)__cvta_generic_to_shared(smem);
    const uint32_t xs_u  = smem_u + OFF_XS * 4;
    const uint32_t w1s_u = smem_u + OFF_XLT * 4;
    const uint32_t w2s_u = smem_u + OFF_W * 4;

    const int t   = threadIdx.x;
    const int bid = blockIdx.x;
    const int bb  = bid / 200;
    const int hw0 = (bid % 200) * P_PIX;

    const int tx = t & 7;       // pixel group: p = tx*4..+3
    const int ty = t >> 3;      // 0..31
    const int lane = t & 31;
    const int warp = t >> 5;

    // ---- load x tile [256][XSS] via cp.async (no reg roundtrip) ----
    const float* xg = x + ((size_t)bb * C_DIM) * HW_DIM + hw0;
#pragma unroll 2
    for (int i = t; i < C_DIM * 8; i += NTHREADS) {
        int c = i >> 3, seg = i & 7;
        cp16(xs_u + (c * 9 + seg) * 16, xg + (size_t)c * HW_DIM + seg * 4);
    }

    // ========== Stage A: h[m][p] = sum_c w1[m][c]*x[c][p]  (c ascending, FMA) ==========
    float a[4][4];
#pragma unroll
    for (int i = 0; i < 4; ++i)
#pragma unroll
        for (int j = 0; j < 4; ++j) a[i][j] = 0.f;

    float* w1s = xl_t;   // staging aliases xl_t region during stage A
    for (int c0 = 0; c0 < C_DIM; c0 += 64) {
        __syncthreads();
#pragma unroll 2
        for (int i = t; i < 2048; i += NTHREADS)
            cp16(w1s_u + i * 16, (const float4*)d_w1t + c0 * 32 + i);
        cp_wait_all();
        __syncthreads();
#pragma unroll 4
        for (int cc = 0; cc < 64; ++cc) {
            float4 wv = ((const float4*)w1s)[cc * 32 + ty];
            float4 xv = ((const float4*)xs)[(c0 + cc) * 9 + tx];
            float wr[4] = {wv.x, wv.y, wv.z, wv.w};
            float xr[4] = {xv.x, xv.y, xv.z, xv.w};
#pragma unroll
            for (int i = 0; i < 4; ++i)
#pragma unroll
                for (int j = 0; j < 4; ++j)
                    a[i][j] = __fmaf_rn(wr[i], xr[j], a[i][j]);
        }
    }
    // hb lives in its own region -> safe to write now
#pragma unroll
    for (int i = 0; i < 4; ++i) {
        int m = ty * 4 + i;
        float bs = d_b1[m];
#pragma unroll
        for (int j = 0; j < 4; ++j)
            hb[m * P_PIX + tx * 4 + j] = __fadd_rn(a[i][j], bs);
    }

    // ========== Stage B: x_[c'][p] = sum_m w2[c'][m]*h[m][p]  (m ascending, FMA) ==========
    float b[8][4];
#pragma unroll
    for (int i = 0; i < 8; ++i)
#pragma unroll
        for (int j = 0; j < 4; ++j) b[i][j] = 0.f;

    for (int m0 = 0; m0 < MED_DIM; m0 += 16) {
        __syncthreads();
#pragma unroll 2
        for (int i = t; i < 1024; i += NTHREADS)
            cp16(w2s_u + i * 16, (const float4*)d_w2t + m0 * 64 + i);
        cp_wait_all();
        __syncthreads();
#pragma unroll 4
        for (int mm = 0; mm < 16; ++mm) {
            float4 hv = ((const float4*)hb)[(m0 + mm) * 8 + tx];
            float4 w0 = ((const float4*)w2s)[mm * 64 + ty * 2];
            float4 w1v = ((const float4*)w2s)[mm * 64 + ty * 2 + 1];
            float wr[8] = {w0.x, w0.y, w0.z, w0.w, w1v.x, w1v.y, w1v.z, w1v.w};
            float hr[4] = {hv.x, hv.y, hv.z, hv.w};
#pragma unroll
            for (int i = 0; i < 8; ++i)
#pragma unroll
                for (int j = 0; j < 4; ++j)
                    b[i][j] = __fmaf_rn(wr[i], hr[j], b[i][j]);
        }
    }

    // ---- epilogue: bias, write x_ transposed [p][c] (w1s region dead) ----
#pragma unroll
    for (int i = 0; i < 8; ++i) {
        int cp = ty * 8 + i;
        float bs = d_b2[cp];
#pragma unroll
        for (int j = 0; j < 4; ++j) {
            float v = __fadd_rn(b[i][j], bs);
            xl_t[(tx * 4 + j) * 256 + cp] = v;
        }
    }
    __syncthreads();

    // ========== register-resident bitonic sort: one warp per pixel (4 px/warp) ==========
    // element e = lane*8 + r ; P = (sigmoid_bits << 8) | (255 ^ c) ; key desc, c asc
#pragma unroll 1
    for (int q = 0; q < 4; ++q) {
        int p = warp * 4 + q;
        const float* row = xl_t + p * 256 + lane * 8;
        float4 v0 = *(const float4*)row;
        float4 v1 = *(const float4*)(row + 4);
        float vv[8] = {v0.x, v0.y, v0.z, v0.w, v1.x, v1.y, v1.z, v1.w};
        unsigned long long P[8];
#pragma unroll
        for (int r = 0; r < 8; ++r) {
            unsigned int kb = __float_as_uint(sigmoid_xla(vv[r]));
            P[r] = ((unsigned long long)kb << 8) |
                   (unsigned long long)(0xFF ^ (lane * 8 + r));
        }

        // ---- k = 2: local j=1, up = ((e&2)==0) = ((r&2)==0), compile-time ----
        ce(P[0], P[1], true);  ce(P[2], P[3], false);
        ce(P[4], P[5], true);  ce(P[6], P[7], false);

        // ---- k = 4: local j=2,1, up = ((r&4)==0), compile-time ----
        ce(P[0], P[2], true);  ce(P[1], P[3], true);
        ce(P[4], P[6], false); ce(P[5], P[7], false);
        ce(P[0], P[1], true);  ce(P[2], P[3], true);
        ce(P[4], P[5], false); ce(P[6], P[7], false);

        // ---- k = 8..256: shfl levels (j>=8) + uniform-up local levels ----
#pragma unroll 1
        for (int k = 8; k <= 256; k <<= 1) {
#pragma unroll 1
            for (int j = k >> 1; j >= 8; j >>= 1) {
                int m = j >> 3;
                bool km = ((lane & (k >> 3)) == 0) == ((lane & m) == 0);
#pragma unroll
                for (int r = 0; r < 8; ++r) {
                    unsigned long long qv = __shfl_xor_sync(0xFFFFFFFFu, P[r], m);
                    P[r] = ((P[r] > qv) == km) ? P[r] : qv;
                }
            }
            // local levels: k>=8 -> up uniform across r (depends on lane only)
            bool upL = (((lane << 3) & k) == 0);
            ce(P[0], P[4], upL); ce(P[1], P[5], upL);
            ce(P[2], P[6], upL); ce(P[3], P[7], upL);
            ce(P[0], P[2], upL); ce(P[1], P[3], upL);
            ce(P[4], P[6], upL); ce(P[5], P[7], upL);
            ce(P[0], P[1], upL); ce(P[2], P[3], upL);
            ce(P[4], P[5], upL); ce(P[6], P[7], upL);
        }

        // element e now holds rank e; emit channel bytes, ranks lane*8..lane*8+7
        unsigned long long wbits = 0;
#pragma unroll
        for (int r = 0; r < 8; ++r)
            wbits |= (unsigned long long)(0xFFu ^ (unsigned)(P[r] & 0xFFu)) << (8 * r);
        *(unsigned long long*)(sidx2 + p * 256 + lane * 8) = wbits;
    }
    __syncthreads();

    // ---- gather (rank-major lanes): prod[r][p] = x[c]*x_[c] ; stride-33 staging ----
#pragma unroll 4
    for (int it = 0; it < 16; ++it) {
        int task = t + NTHREADS * it;      // 32 px * 128 ranks
        int r = task & 127;
        int p = task >> 7;
        int c = sidx2[p * 256 + r];
        prod[r * 33 + p] = __fmul_rn(xs[c * XSS + p], xl_t[p * 256 + c]);
    }
    __syncthreads();

    // ---- write (pixel-major lanes): fully coalesced ----
#pragma unroll 4
    for (int it = 0; it < 16; ++it) {
        int task = t + NTHREADS * it;
        int p = task & 31;
        int rr = task >> 5;
        out[((size_t)(bb * K_OUT + rr)) * HW_DIM + hw0 + p] = prod[rr * 33 + p];
    }
}

extern "C" void kernel_launch(void* const* d_in, const int* in_sizes, int n_in,
                              void* d_out, int out_size) {
    const float* x  = (const float*)d_in[0];
    const float* w1 = (const float*)d_in[1];
    const float* b1 = (const float*)d_in[2];
    const float* w2 = (const float*)d_in[3];
    const float* b2 = (const float*)d_in[4];
    float* out = (float*)d_out;

    cudaFuncSetAttribute(csc_main_kernel,
                         cudaFuncAttributeMaxDynamicSharedMemorySize, SMEM_BYTES);
    prep_kernel<<<C_DIM, NTHREADS>>>(w1, b1, w2, b2);
    csc_main_kernel<<<(B_DIM * HW_DIM) / P_PIX, NTHREADS, SMEM_BYTES>>>(x, out);
}